// round 1
// baseline (speedup 1.0000x reference)
#include <cuda_runtime.h>

#define N_SPARSE 16
#define N_VARLEN 4
#define SEQ_L 50
#define VOCAB 1000000
#define EPSV 1e-8f
#define ROW_LEN (N_SPARSE + N_VARLEN * SEQ_L)   // 216
#define OUT_LEN (N_SPARSE + N_VARLEN)           // 20
#define ROWS_PER_BLOCK 8
#define THREADS (ROWS_PER_BLOCK * 32)

__global__ __launch_bounds__(THREADS) void emb_pool_kernel(
    const int* __restrict__ X,
    const float* __restrict__ sparse_tables,
    const float* __restrict__ varlen_tables,
    float* __restrict__ out)
{
    __shared__ int sx[ROWS_PER_BLOCK][ROW_LEN];

    const int tid  = threadIdx.x;
    const int base = blockIdx.x * ROWS_PER_BLOCK;

    // Coalesced stage of 8 rows of X into shared memory
    const int* Xb = X + (size_t)base * ROW_LEN;
    #pragma unroll
    for (int i = tid; i < ROWS_PER_BLOCK * ROW_LEN; i += THREADS)
        sx[i / ROW_LEN][i % ROW_LEN] = Xb[i];
    __syncthreads();

    const int w    = tid >> 5;
    const int lane = tid & 31;
    const int row  = base + w;
    float* orow = out + (size_t)row * OUT_LEN;

    // ---- Sparse features: lanes 0..15 each do one gather ----
    if (lane < N_SPARSE) {
        int id = sx[w][lane];
        orow[lane] = __ldg(sparse_tables + (size_t)lane * VOCAB + id);
    }

    // ---- Varlen features: load phase (all gathers in flight), then reduce ----
    float s[N_VARLEN], c[N_VARLEN];

    #pragma unroll
    for (int v = 0; v < N_VARLEN; v++) {
        const int* ids = &sx[w][N_SPARSE + v * SEQ_L];
        float sv = 0.f, cv = 0.f;
        int id0 = ids[lane];
        if (id0 != 0) {
            sv = __ldg(varlen_tables + (size_t)v * VOCAB + id0);
            cv = 1.f;
        }
        if (lane < SEQ_L - 32) {
            int id1 = ids[32 + lane];
            if (id1 != 0) {
                sv += __ldg(varlen_tables + (size_t)v * VOCAB + id1);
                cv += 1.f;
            }
        }
        s[v] = sv;
        c[v] = cv;
    }

    // Warp reductions (per feature)
    #pragma unroll
    for (int v = 0; v < N_VARLEN; v++) {
        float sv = s[v], cv = c[v];
        #pragma unroll
        for (int o = 16; o; o >>= 1) {
            sv += __shfl_xor_sync(0xffffffffu, sv, o);
            cv += __shfl_xor_sync(0xffffffffu, cv, o);
        }
        if (lane == 0)
            orow[N_SPARSE + v] = sv / (cv + EPSV);
    }
}

extern "C" void kernel_launch(void* const* d_in, const int* in_sizes, int n_in,
                              void* d_out, int out_size)
{
    const int*   X  = (const int*)d_in[0];
    const float* st = (const float*)d_in[1];
    const float* vt = (const float*)d_in[2];
    float* out = (float*)d_out;

    const int B = in_sizes[0] / ROW_LEN;   // 16384
    const int grid = B / ROWS_PER_BLOCK;   // 2048

    emb_pool_kernel<<<grid, THREADS>>>(X, st, vt, out);
}